// round 6
// baseline (speedup 1.0000x reference)
#include <cuda_runtime.h>
#include <cstdint>

__device__ float g_Weff[24];
__device__ float g_beff[4];

#define ALPHA1 1.2566f
#define ALPHA2 1.5f
#define ALPHA3 0.9f
#define S_STAR 20.0f
#define TAU    4.0f

#define TILE       512              // outputs per tile
#define ROW_BYTES  12288            // 6*TILE*4  (row data per tile)
#define NSTAGE     4

// ---- helpers --------------------------------------------------------------
__device__ __forceinline__ void griddep_wait() {
    asm volatile("griddepcontrol.wait;" ::: "memory");
}
__device__ __forceinline__ void griddep_launch_dependents() {
    asm volatile("griddepcontrol.launch_dependents;");
}
__device__ __forceinline__ uint32_t smem_u32(const void* p) {
    uint32_t a;
    asm("{ .reg .u64 t; cvta.to.shared.u64 t, %1; cvt.u32.u64 %0, t; }"
        : "=r"(a) : "l"(p));
    return a;
}
__device__ __forceinline__ void mbar_wait(uint32_t mbar, uint32_t parity) {
    uint32_t done;
    asm volatile(
        "{\n\t.reg .pred p;\n\t"
        "mbarrier.try_wait.parity.acquire.cta.shared::cta.b64 p, [%1], %2;\n\t"
        "selp.b32 %0, 1, 0, p;\n\t}"
        : "=r"(done) : "r"(mbar), "r"(parity) : "memory");
    if (!done) {
        asm volatile(
            "{\n\t.reg .pred P1;\n\t"
            "WL_%=:\n\t"
            "mbarrier.try_wait.parity.acquire.cta.shared::cta.b64 P1, [%0], %1, 0x989680;\n\t"
            "@P1 bra.uni WD_%=;\n\t"
            "bra.uni WL_%=;\n\t"
            "WD_%=:\n\t}"
            :: "r"(mbar), "r"(parity) : "memory");
    }
}

// ---------------------------------------------------------------------------
// Prelude: fold the affine chain; early PDL trigger for overlap.
// ---------------------------------------------------------------------------
__global__ __launch_bounds__(256) void fold_weights_kernel(
    const float* __restrict__ W1, const float* __restrict__ b1,
    const float* __restrict__ W2, const float* __restrict__ b2,
    const float* __restrict__ W3, const float* __restrict__ b3) {
    griddep_launch_dependents();

    __shared__ float sW2[100 * 50];
    __shared__ float sW1[50 * 6];
    __shared__ float sW3[4 * 100];
    __shared__ float sb1[50];
    __shared__ float sb2[100];
    __shared__ float sT[4 * 50];

    const int t = threadIdx.x;
    {
        const float4* W2v = reinterpret_cast<const float4*>(W2);
        float4* sW2v = reinterpret_cast<float4*>(sW2);
        for (int i = t; i < 1250; i += 256) sW2v[i] = W2v[i];
        for (int i = t; i < 300; i += 256) sW1[i] = W1[i];
        for (int i = t; i < 400; i += 256) sW3[i] = W3[i];
        if (t < 50)             sb1[t] = b1[t];
        if (t >= 64 && t < 164) sb2[t - 64] = b2[t - 64];
    }
    __syncthreads();

    if (t < 200) {
        const int k = t / 50, c = t % 50;
        float s0 = 0.f, s1 = 0.f;
        #pragma unroll
        for (int j = 0; j < 100; j += 2) {
            s0 = fmaf(sW3[k * 100 + j],     sW2[j * 50 + c],       s0);
            s1 = fmaf(sW3[k * 100 + j + 1], sW2[(j + 1) * 50 + c], s1);
        }
        sT[t] = s0 + s1;
    }
    __syncthreads();

    if (t < 24) {
        const int k = t / 6, i = t % 6;
        float s = 0.f;
        #pragma unroll
        for (int c = 0; c < 50; ++c) s = fmaf(sT[k * 50 + c], sW1[c * 6 + i], s);
        g_Weff[t] = s;
    }
    if (t >= 32 && t < 36) {
        const int k = t - 32;
        float s = b3[k];
        #pragma unroll
        for (int c = 0; c < 50; ++c) s = fmaf(sT[k * 50 + c], sb1[c], s);
        #pragma unroll
        for (int j = 0; j < 100; ++j) s = fmaf(sW3[k * 100 + j], sb2[j], s);
        g_beff[k] = s;
    }
}

// ---------------------------------------------------------------------------
// Persistent hybrid kernel:
//   rows    -> 4-stage TMA pipeline into smem (12KB/stage), conflict-free LDS
//   columns -> direct coalesced LDG float2, issued before the stage wait
// 592 CTAs (4/SM), 256 threads, 2 outputs/thread.
// ---------------------------------------------------------------------------
__global__ __launch_bounds__(256, 4) void barrier_main_kernel(
    const float* __restrict__ z, float* __restrict__ out,
    int B, int ntiles) {
    __shared__ __align__(128) float s_row[NSTAGE * (ROW_BYTES / 4)];
    __shared__ __align__(8) unsigned long long s_full[NSTAGE];

    const int tid = threadIdx.x;
    const uint32_t fullb = smem_u32(&s_full[0]);
    const uint32_t rowb  = smem_u32(s_row);

    if (tid == 0) {
        #pragma unroll
        for (int s = 0; s < NSTAGE; ++s)
            asm volatile("mbarrier.init.shared.b64 [%0], %1;"
                         :: "r"(fullb + 8u * s), "r"(1) : "memory");
    }
    __syncthreads();
    if (tid == 0)
        asm volatile("fence.proxy.async.shared::cta;" ::: "memory");

    auto issue_rows = [&](int t, int s) {
        const uint32_t mb = fullb + 8u * s;
        asm volatile("mbarrier.arrive.expect_tx.shared.b64 _, [%0], %1;"
                     :: "r"(mb), "r"(ROW_BYTES) : "memory");
        asm volatile(
            "cp.async.bulk.shared::cta.global.mbarrier::complete_tx::bytes "
            "[%0], [%1], %2, [%3];"
            :: "r"(rowb + (uint32_t)s * ROW_BYTES),
               "l"(z + (size_t)6 * TILE * t), "r"(ROW_BYTES),
               "r"(mb) : "memory");
    };

    // Prologue: fill all 4 stages (touches only z -> independent of fold)
    if (tid == 0) {
        #pragma unroll
        for (int j = 0; j < NSTAGE; ++j) {
            const int t = blockIdx.x + j * gridDim.x;
            if (t < ntiles) issue_rows(t, j);
        }
    }

    // Fold results
    griddep_wait();
    float W[24], bf[4];
    #pragma unroll
    for (int i = 0; i < 24; ++i) W[i] = g_Weff[i];
    #pragma unroll
    for (int i = 0; i < 4; ++i) bf[i] = g_beff[i];

    const float d3u1 = TAU * ALPHA3;
    const float d3u2 = TAU * ALPHA1;
    const float d3u3 = 1.f - TAU * (ALPHA2 + ALPHA3);
    const float d3u4 = -TAU * ALPHA1;
    const float d3u5 = TAU * ALPHA2 - 1.f;
    const float invA0 = -1.f / TAU;
    const float invA1 = -1.f / (TAU * ALPHA3);

    const float2* __restrict__ z2 = reinterpret_cast<const float2*>(z);
    const int halfB = B >> 1;           // float2 stride per component

    int k = 0;
    for (int t = blockIdx.x; t < ntiles; t += gridDim.x, ++k) {
        const int s = k & (NSTAGE - 1);

        // Columns: coalesced direct loads (overlap with stage wait)
        float2 cv[5];
        #pragma unroll
        for (int i = 0; i < 5; ++i)
            cv[i] = z2[(size_t)(i + 1) * halfB + (size_t)(TILE / 2) * t + tid];

        mbar_wait(fullb + 8u * s, (k >> 2) & 1);

        // Rows: conflict-free LDS.128 (quad stride 3, gcd(3,8)=1)
        const float4* row4 = reinterpret_cast<const float4*>(
            s_row + s * (ROW_BYTES / 4));
        float rf[12];
        #pragma unroll
        for (int q = 0; q < 3; ++q) {
            float4 v = row4[3 * tid + q];
            rf[4 * q + 0] = v.x; rf[4 * q + 1] = v.y;
            rf[4 * q + 2] = v.z; rf[4 * q + 3] = v.w;
        }

        float res[2];
        #pragma unroll
        for (int l = 0; l < 2; ++l) {
            float u0 = bf[0], u1 = bf[1], u2 = bf[2], u3 = bf[3];
            #pragma unroll
            for (int i = 0; i < 6; ++i) {
                const float zi = rf[6 * l + i];
                u0 = fmaf(W[i],      zi, u0);
                u1 = fmaf(W[6 + i],  zi, u1);
                u2 = fmaf(W[12 + i], zi, u2);
                u3 = fmaf(W[18 + i], zi, u3);
            }
            const float x1 = l ? cv[0].y : cv[0].x;
            const float x2 = l ? cv[1].y : cv[1].x;
            const float x3 = l ? cv[2].y : cv[2].x;
            const float x4 = l ? cv[3].y : cv[3].x;
            const float x5 = l ? cv[4].y : cv[4].x;

            const float fX2 = x1 - x3;
            const float fX3 = ALPHA3 * x1 + ALPHA1 * x2 - ALPHA2 * x3;
            const float fX4 = x3 - x5;
            const float fX5 = ALPHA3 * x3 + ALPHA1 * x4 - ALPHA2 * x5;

            const float eta1 = x2 + S_STAR - TAU * (x3 - x1);
            const float bb1  = fX2 - TAU * fX3 + u1 * eta1;

            const float eta2a = x4 + S_STAR - TAU * (x5 - x3);
            const float eta2b = d3u1 * x1 + d3u2 * x2 + d3u3 * x3
                              + d3u4 * x4 + d3u5 * x5;
            const float bb2   = d3u2 * fX2 + d3u3 * fX3 + d3u4 * fX4 + d3u5 * fX5
                              + u2 * eta2a + u3 * eta2b;

            const float lb = fmaxf(bb1 * invA0, bb2 * invA1);
            res[l] = fminf(fmaxf(2.f * u0, lb), 1e30f);
        }

        reinterpret_cast<float2*>(out)[(size_t)(TILE / 2) * t + tid] =
            make_float2(res[0], res[1]);

        __syncthreads();   // stage s fully consumed before reissue
        if (tid == 0) {
            const int tn = t + NSTAGE * gridDim.x;
            if (tn < ntiles) issue_rows(tn, s);
        }
    }
}

// ---------------------------------------------------------------------------
// Inputs (metadata order): z, tilde_vh, W1, b1, W2, b2, W3, b3
// ---------------------------------------------------------------------------
extern "C" void kernel_launch(void* const* d_in, const int* in_sizes, int n_in,
                              void* d_out, int out_size) {
    const float* z  = (const float*)d_in[0];
    const float* W1 = (const float*)d_in[2];
    const float* b1 = (const float*)d_in[3];
    const float* W2 = (const float*)d_in[4];
    const float* b2 = (const float*)d_in[5];
    const float* W3 = (const float*)d_in[6];
    const float* b3 = (const float*)d_in[7];
    float* out = (float*)d_out;

    const int B      = in_sizes[0] / 6;   // 1048576
    const int ntiles = B / TILE;          // 2048

    fold_weights_kernel<<<1, 256>>>(W1, b1, W2, b2, W3, b3);

    int blocks = 592;                     // 4 CTAs/SM x 148 SMs
    if (blocks > ntiles) blocks = ntiles;

    cudaLaunchConfig_t cfg = {};
    cfg.gridDim  = dim3(blocks);
    cfg.blockDim = dim3(256);
    cfg.dynamicSmemBytes = 0;
    cfg.stream = 0;
    cudaLaunchAttribute attrs[1];
    attrs[0].id = cudaLaunchAttributeProgrammaticStreamSerialization;
    attrs[0].val.programmaticStreamSerializationAllowed = 1;
    cfg.attrs = attrs;
    cfg.numAttrs = 1;

    cudaLaunchKernelEx(&cfg, barrier_main_kernel, z, out, B, ntiles);
}

// round 7
// speedup vs baseline: 1.0151x; 1.0151x over previous
#include <cuda_runtime.h>
#include <cstdint>

__device__ float g_Weff[24];
__device__ float g_beff[4];

#define ALPHA1 1.2566f
#define ALPHA2 1.5f
#define ALPHA3 0.9f
#define S_STAR 20.0f
#define TAU    4.0f

// ---- PDL helpers ----------------------------------------------------------
__device__ __forceinline__ void griddep_wait() {
    asm volatile("griddepcontrol.wait;" ::: "memory");
}
__device__ __forceinline__ void griddep_launch_dependents() {
    asm volatile("griddepcontrol.launch_dependents;");
}

// ---------------------------------------------------------------------------
// Prelude: fold the affine chain; early PDL trigger for overlap.
// ---------------------------------------------------------------------------
__global__ __launch_bounds__(256) void fold_weights_kernel(
    const float* __restrict__ W1, const float* __restrict__ b1,
    const float* __restrict__ W2, const float* __restrict__ b2,
    const float* __restrict__ W3, const float* __restrict__ b3) {
    griddep_launch_dependents();

    __shared__ float sW2[100 * 50];
    __shared__ float sW1[50 * 6];
    __shared__ float sW3[4 * 100];
    __shared__ float sb1[50];
    __shared__ float sb2[100];
    __shared__ float sT[4 * 50];

    const int t = threadIdx.x;
    {
        const float4* W2v = reinterpret_cast<const float4*>(W2);
        float4* sW2v = reinterpret_cast<float4*>(sW2);
        for (int i = t; i < 1250; i += 256) sW2v[i] = W2v[i];
        for (int i = t; i < 300; i += 256) sW1[i] = W1[i];
        for (int i = t; i < 400; i += 256) sW3[i] = W3[i];
        if (t < 50)             sb1[t] = b1[t];
        if (t >= 64 && t < 164) sb2[t - 64] = b2[t - 64];
    }
    __syncthreads();

    if (t < 200) {
        const int k = t / 50, c = t % 50;
        float s0 = 0.f, s1 = 0.f;
        #pragma unroll
        for (int j = 0; j < 100; j += 2) {
            s0 = fmaf(sW3[k * 100 + j],     sW2[j * 50 + c],       s0);
            s1 = fmaf(sW3[k * 100 + j + 1], sW2[(j + 1) * 50 + c], s1);
        }
        sT[t] = s0 + s1;
    }
    __syncthreads();

    if (t < 24) {
        const int k = t / 6, i = t % 6;
        float s = 0.f;
        #pragma unroll
        for (int c = 0; c < 50; ++c) s = fmaf(sT[k * 50 + c], sW1[c * 6 + i], s);
        g_Weff[t] = s;
    }
    if (t >= 32 && t < 36) {
        const int k = t - 32;
        float s = b3[k];
        #pragma unroll
        for (int c = 0; c < 50; ++c) s = fmaf(sT[k * 50 + c], sb1[c], s);
        #pragma unroll
        for (int j = 0; j < 100; ++j) s = fmaf(sW3[k * 100 + j], sb2[j], s);
        g_beff[k] = s;
    }
}

// ---------------------------------------------------------------------------
// Main kernel. 1024 outputs per CTA, 4 per thread.
// Rows: COALESCED LDG.128 (lane-contiguous, 4 wf/instr) -> smem scatter into
//       7-quad-padded layout -> conflict-free LDS.128 gather (quad base 7*tid,
//       odd stride => all 8 banks distinct, every wavefront byte useful).
// Cols: direct coalesced LDG.128. Store: STG.128.
// ---------------------------------------------------------------------------
__global__ __launch_bounds__(256, 4) void barrier_main_kernel(
    const float* __restrict__ z, float* __restrict__ out, int B) {
    __shared__ __align__(16) float4 s_row[256 * 7];   // 28 KB padded

    const int tid = threadIdx.x;
    const int blk = blockIdx.x;
    const float4* __restrict__ z4 = reinterpret_cast<const float4*>(z);

    // ---- Rows: coalesced load + padded scatter ----
    // CTA covers outputs [1024*blk, 1024*(blk+1)) = 6144 floats = 1536 quads.
    const size_t rowQ = (size_t)blk * 1536;
    #pragma unroll
    for (int r = 0; r < 6; ++r) {
        const int g = 256 * r + tid;          // quad index within tile
        const float4 v = z4[rowQ + g];        // lane-contiguous: 4 wf
        const int tt = g / 6, q = g - 6 * tt; // owner thread, position
        s_row[7 * tt + q] = v;
    }

    // ---- Cols: direct coalesced loads (overlap with smem/sync/fold) ----
    const int nv = B >> 2;
    const int j4 = blk * 256 + tid;           // float4 index in column space
    float4 c[5];
    #pragma unroll
    for (int i = 0; i < 5; ++i)
        c[i] = z4[(size_t)(i + 1) * nv + j4];

    // Fold results (fold kernel ran concurrently; PDL wait)
    griddep_wait();
    float W[24], bf[4];
    #pragma unroll
    for (int i = 0; i < 24; ++i) W[i] = g_Weff[i];
    #pragma unroll
    for (int i = 0; i < 4; ++i) bf[i] = g_beff[i];

    __syncthreads();

    // ---- Rows: conflict-free gather ----
    float rf[24];
    #pragma unroll
    for (int q = 0; q < 6; ++q) {
        const float4 v = s_row[7 * tid + q];
        rf[4 * q + 0] = v.x; rf[4 * q + 1] = v.y;
        rf[4 * q + 2] = v.z; rf[4 * q + 3] = v.w;
    }

    float xc[5][4];
    #pragma unroll
    for (int i = 0; i < 5; ++i) {
        xc[i][0] = c[i].x; xc[i][1] = c[i].y;
        xc[i][2] = c[i].z; xc[i][3] = c[i].w;
    }

    const float d3u1 = TAU * ALPHA3;
    const float d3u2 = TAU * ALPHA1;
    const float d3u3 = 1.f - TAU * (ALPHA2 + ALPHA3);
    const float d3u4 = -TAU * ALPHA1;
    const float d3u5 = TAU * ALPHA2 - 1.f;
    const float invA0 = -1.f / TAU;
    const float invA1 = -1.f / (TAU * ALPHA3);

    float res[4];
    #pragma unroll
    for (int l = 0; l < 4; ++l) {
        float u0 = bf[0], u1 = bf[1], u2 = bf[2], u3 = bf[3];
        #pragma unroll
        for (int i = 0; i < 6; ++i) {
            const float zi = rf[6 * l + i];
            u0 = fmaf(W[i],      zi, u0);
            u1 = fmaf(W[6 + i],  zi, u1);
            u2 = fmaf(W[12 + i], zi, u2);
            u3 = fmaf(W[18 + i], zi, u3);
        }
        const float x1 = xc[0][l], x2 = xc[1][l], x3 = xc[2][l];
        const float x4 = xc[3][l], x5 = xc[4][l];

        const float fX2 = x1 - x3;
        const float fX3 = ALPHA3 * x1 + ALPHA1 * x2 - ALPHA2 * x3;
        const float fX4 = x3 - x5;
        const float fX5 = ALPHA3 * x3 + ALPHA1 * x4 - ALPHA2 * x5;

        const float eta1 = x2 + S_STAR - TAU * (x3 - x1);
        const float bb1  = fX2 - TAU * fX3 + u1 * eta1;

        const float eta2a = x4 + S_STAR - TAU * (x5 - x3);
        const float eta2b = d3u1 * x1 + d3u2 * x2 + d3u3 * x3
                          + d3u4 * x4 + d3u5 * x5;
        const float bb2   = d3u2 * fX2 + d3u3 * fX3 + d3u4 * fX4 + d3u5 * fX5
                          + u2 * eta2a + u3 * eta2b;

        const float lb = fmaxf(bb1 * invA0, bb2 * invA1);
        res[l] = fminf(fmaxf(2.f * u0, lb), 1e30f);
    }

    reinterpret_cast<float4*>(out)[j4] =
        make_float4(res[0], res[1], res[2], res[3]);
}

// ---------------------------------------------------------------------------
// Inputs (metadata order): z, tilde_vh, W1, b1, W2, b2, W3, b3
// ---------------------------------------------------------------------------
extern "C" void kernel_launch(void* const* d_in, const int* in_sizes, int n_in,
                              void* d_out, int out_size) {
    const float* z  = (const float*)d_in[0];
    const float* W1 = (const float*)d_in[2];
    const float* b1 = (const float*)d_in[3];
    const float* W2 = (const float*)d_in[4];
    const float* b2 = (const float*)d_in[5];
    const float* W3 = (const float*)d_in[6];
    const float* b3 = (const float*)d_in[7];
    float* out = (float*)d_out;

    const int B = in_sizes[0] / 6;        // 1048576
    const int blocks = B >> 10;           // 1024 outputs per CTA

    fold_weights_kernel<<<1, 256>>>(W1, b1, W2, b2, W3, b3);

    cudaLaunchConfig_t cfg = {};
    cfg.gridDim  = dim3(blocks);
    cfg.blockDim = dim3(256);
    cfg.dynamicSmemBytes = 0;
    cfg.stream = 0;
    cudaLaunchAttribute attrs[1];
    attrs[0].id = cudaLaunchAttributeProgrammaticStreamSerialization;
    attrs[0].val.programmaticStreamSerializationAllowed = 1;
    cfg.attrs = attrs;
    cfg.numAttrs = 1;

    cudaLaunchKernelEx(&cfg, barrier_main_kernel, z, out, B);
}